// round 13
// baseline (speedup 1.0000x reference)
#include <cuda_runtime.h>
#include <cstddef>

#define BB 2048
#define TT 1024
#define DD 64
#define HH 32

typedef unsigned long long u64;

// scratch: gate preactivations (layer0 then reused for layer1-input), all h0
__device__ float g_gx0[(size_t)BB * TT * 96];
__device__ float g_gx1[(size_t)BB * TT * 96];
__device__ float g_h0[(size_t)BB * TT * 32];

__device__ __forceinline__ u64 ffma2(u64 a, u64 b, u64 c) {
    u64 d;
    asm("fma.rn.f32x2 %0, %1, %2, %3;" : "=l"(d) : "l"(a), "l"(b), "l"(c));
    return d;
}
__device__ __forceinline__ u64 pack2(float lo, float hi) {
    u64 r;
    asm("mov.b64 %0, {%1, %2};" : "=l"(r) : "f"(lo), "f"(hi));
    return r;
}
__device__ __forceinline__ float sum2(u64 v) {
    float a, b;
    asm("mov.b64 {%0, %1}, %2;" : "=f"(a), "=f"(b) : "l"(v));
    return a + b;
}
__device__ __forceinline__ float fast_sigmoid(float x) {
    float e;
    asm("ex2.approx.f32 %0, %1;" : "=f"(e) : "f"(-1.4426950408889634f * x));
    float r;
    asm("rcp.approx.f32 %0, %1;" : "=f"(r) : "f"(1.0f + e));
    return r;
}
__device__ __forceinline__ float fast_tanh(float x) {
    return fmaf(2.0f, fast_sigmoid(2.0f * x), -1.0f);
}

// ================= Phase A: gx0 = x @ W_ih0^T + b_ih0  (K=64) =================
// 2 blocks/SM via launch_bounds; 8 warps x 128 tokens each, warp-private staging.
__global__ void __launch_bounds__(256, 2)
gx0_kernel(const float* __restrict__ x,
           const float* __restrict__ wih0, const float* __restrict__ bih0)
{
    __shared__ float4 w4[16 * 96];     // [kk][gate] transposed, 24KB
    __shared__ float4 xs[8 * 128];     // per-warp 8 tokens x 16 f4, 16KB

    const int tid = threadIdx.x, warp = tid >> 5, lane = tid & 31;
    for (int i = tid; i < 1536; i += 256) {
        int g = i % 96, kk = i / 96;
        w4[kk * 96 + g] = *(const float4*)(wih0 + g * 64 + kk * 4);
    }
    __syncthreads();
    const float b0 = bih0[lane], b1 = bih0[32 + lane], b2 = bih0[64 + lane];

    const int row = blockIdx.x;
    const float4* xg = (const float4*)(x + (size_t)row * TT * DD) + warp * 2048;
    float* gw = g_gx0 + ((size_t)row * TT + warp * 128) * 96;
    float4* xsw = xs + warp * 128;

    float4 xb[4];
#pragma unroll
    for (int i = 0; i < 4; i++) xb[i] = xg[i * 32 + lane];
    xg += 128;

    for (int it = 0; it < 16; it++) {
#pragma unroll
        for (int i = 0; i < 4; i++) xsw[i * 32 + lane] = xb[i];
        __syncwarp();
        if (it + 1 < 16) {
#pragma unroll
            for (int i = 0; i < 4; i++) xb[i] = xg[i * 32 + lane];
            xg += 128;
        }
        u64 a0[8], a1[8], a2[8];
#pragma unroll
        for (int t = 0; t < 8; t++) {
            a0[t] = pack2(b0, 0.f); a1[t] = pack2(b1, 0.f); a2[t] = pack2(b2, 0.f);
        }
#pragma unroll 4
        for (int kk = 0; kk < 16; kk++) {
            ulonglong2 wr = *(const ulonglong2*)(w4 + kk * 96 + lane);
            ulonglong2 wz = *(const ulonglong2*)(w4 + kk * 96 + 32 + lane);
            ulonglong2 wn = *(const ulonglong2*)(w4 + kk * 96 + 64 + lane);
#pragma unroll
            for (int t = 0; t < 8; t++) {
                ulonglong2 xv = *(const ulonglong2*)(xsw + t * 16 + kk);
                a0[t] = ffma2(wr.x, xv.x, a0[t]); a0[t] = ffma2(wr.y, xv.y, a0[t]);
                a1[t] = ffma2(wz.x, xv.x, a1[t]); a1[t] = ffma2(wz.y, xv.y, a1[t]);
                a2[t] = ffma2(wn.x, xv.x, a2[t]); a2[t] = ffma2(wn.y, xv.y, a2[t]);
            }
        }
#pragma unroll
        for (int t = 0; t < 8; t++) {
            float* o = gw + (it * 8 + t) * 96;
            o[lane] = sum2(a0[t]); o[32 + lane] = sum2(a1[t]); o[64 + lane] = sum2(a2[t]);
        }
        __syncwarp();
    }
}

// ================= Phase C: gxl1 = h0_all @ W_ih1^T + b_ih1  (K=32) =================
__global__ void __launch_bounds__(256, 2)
gxl1_kernel(const float* __restrict__ wih1, const float* __restrict__ bih1)
{
    __shared__ float4 w4[8 * 96];      // 12KB
    __shared__ float4 hsh[8 * 64];     // 8KB: per-warp 8 tokens x 8 f4

    const int tid = threadIdx.x, warp = tid >> 5, lane = tid & 31;
    for (int i = tid; i < 768; i += 256) {
        int g = i % 96, kk = i / 96;
        w4[kk * 96 + g] = *(const float4*)(wih1 + g * 32 + kk * 4);
    }
    __syncthreads();
    const float b0 = bih1[lane], b1 = bih1[32 + lane], b2 = bih1[64 + lane];

    const int row = blockIdx.x;
    const float4* hg = (const float4*)(g_h0 + (size_t)row * TT * 32) + warp * 1024;
    float* gw = g_gx1 + ((size_t)row * TT + warp * 128) * 96;
    float4* hsw = hsh + warp * 64;

    float4 hb[2];
#pragma unroll
    for (int i = 0; i < 2; i++) hb[i] = hg[i * 32 + lane];
    hg += 64;

    for (int it = 0; it < 16; it++) {
#pragma unroll
        for (int i = 0; i < 2; i++) hsw[i * 32 + lane] = hb[i];
        __syncwarp();
        if (it + 1 < 16) {
#pragma unroll
            for (int i = 0; i < 2; i++) hb[i] = hg[i * 32 + lane];
            hg += 64;
        }
        u64 a0[8], a1[8], a2[8];
#pragma unroll
        for (int t = 0; t < 8; t++) {
            a0[t] = pack2(b0, 0.f); a1[t] = pack2(b1, 0.f); a2[t] = pack2(b2, 0.f);
        }
#pragma unroll 4
        for (int kk = 0; kk < 8; kk++) {
            ulonglong2 wr = *(const ulonglong2*)(w4 + kk * 96 + lane);
            ulonglong2 wz = *(const ulonglong2*)(w4 + kk * 96 + 32 + lane);
            ulonglong2 wn = *(const ulonglong2*)(w4 + kk * 96 + 64 + lane);
#pragma unroll
            for (int t = 0; t < 8; t++) {
                ulonglong2 hv = *(const ulonglong2*)(hsw + t * 8 + kk);
                a0[t] = ffma2(wr.x, hv.x, a0[t]); a0[t] = ffma2(wr.y, hv.y, a0[t]);
                a1[t] = ffma2(wz.x, hv.x, a1[t]); a1[t] = ffma2(wz.y, hv.y, a1[t]);
                a2[t] = ffma2(wn.x, hv.x, a2[t]); a2[t] = ffma2(wn.y, hv.y, a2[t]);
            }
        }
#pragma unroll
        for (int t = 0; t < 8; t++) {
            float* o = gw + (it * 8 + t) * 96;
            o[lane] = sum2(a0[t]); o[32 + lane] = sum2(a1[t]); o[64 + lane] = sum2(a2[t]);
        }
        __syncwarp();
    }
}

// ================= Phase B: layer-0 recurrence only =================
// 128 blocks x 16 warps x 1 row/warp (4 warps/SMSP). W_hh0 in regs; NO shared weights.
__global__ void __launch_bounds__(512, 1)
rec0_kernel(const float* __restrict__ whh0, const float* __restrict__ bhh0,
            float* __restrict__ out)
{
    __shared__ float hs[16 * 32];
    const int tid = threadIdx.x, warp = tid >> 5, lane = tid & 31;

    u64 wr[16], wz[16], wn[16];        // lane j owns gate rows j, 32+j, 64+j
#pragma unroll
    for (int i = 0; i < 8; i++) {
        ulonglong2 a = *(const ulonglong2*)(whh0 + lane * 32 + i * 4);
        ulonglong2 b = *(const ulonglong2*)(whh0 + (32 + lane) * 32 + i * 4);
        ulonglong2 c = *(const ulonglong2*)(whh0 + (64 + lane) * 32 + i * 4);
        wr[2 * i] = a.x; wr[2 * i + 1] = a.y;
        wz[2 * i] = b.x; wz[2 * i + 1] = b.y;
        wn[2 * i] = c.x; wn[2 * i + 1] = c.y;
    }
    const float bR = bhh0[lane], bZ = bhh0[32 + lane], bN = bhh0[64 + lane];

    const int row = blockIdx.x * 16 + warp;
    float* hw = hs + warp * 32;
    hw[lane] = 0.f;
    float h = 0.f;

    const float* ga = g_gx0 + (size_t)row * TT * 96;
    float* ho = g_h0 + (size_t)row * TT * 32;

    float f0[3], f1[3];                // 2-deep gx prefetch
    f0[0] = ga[lane]; f0[1] = ga[32 + lane]; f0[2] = ga[64 + lane]; ga += 96;
    f1[0] = ga[lane]; f1[1] = ga[32 + lane]; f1[2] = ga[64 + lane]; ga += 96;
    __syncwarp();

#pragma unroll 2
    for (int t = 0; t < TT; t++) {
        float xr, xz, xn;
        if ((t & 1) == 0) { xr = f0[0]; xz = f0[1]; xn = f0[2]; }
        else              { xr = f1[0]; xz = f1[1]; xn = f1[2]; }
        if (t + 2 < TT) {
            if ((t & 1) == 0) { f0[0] = ga[lane]; f0[1] = ga[32 + lane]; f0[2] = ga[64 + lane]; }
            else              { f1[0] = ga[lane]; f1[1] = ga[32 + lane]; f1[2] = ga[64 + lane]; }
            ga += 96;
        }

        u64 gr = pack2(xr + bR, 0.f), gz = pack2(xz + bZ, 0.f), gn = pack2(bN, 0.f);
#pragma unroll
        for (int kk = 0; kk < 8; kk++) {
            ulonglong2 v = *(const ulonglong2*)(hw + kk * 4);
            gr = ffma2(wr[2 * kk], v.x, gr); gr = ffma2(wr[2 * kk + 1], v.y, gr);
            gz = ffma2(wz[2 * kk], v.x, gz); gz = ffma2(wz[2 * kk + 1], v.y, gz);
            gn = ffma2(wn[2 * kk], v.x, gn); gn = ffma2(wn[2 * kk + 1], v.y, gn);
        }
        {
            float r = fast_sigmoid(sum2(gr));
            float z = fast_sigmoid(sum2(gz));
            float n = fast_tanh(xn + r * sum2(gn));   // b_hh_n inside r* (torch GRU)
            h = n + z * (h - n);
        }
        ho[t * 32 + lane] = h;
        __syncwarp();
        hw[lane] = h;
        __syncwarp();
    }
    out[BB + row * HH + lane] = h;     // h_last0
}

// ================= Phase D: layer-1 recurrence + classifier =================
__global__ void __launch_bounds__(512, 1)
rec1_kernel(const float* __restrict__ whh1, const float* __restrict__ bhh1,
            const float* __restrict__ wcls, const float* __restrict__ bcls,
            float* __restrict__ out)
{
    __shared__ float hs[16 * 32];
    const int tid = threadIdx.x, warp = tid >> 5, lane = tid & 31;

    u64 wr[16], wz[16], wn[16];
#pragma unroll
    for (int i = 0; i < 8; i++) {
        ulonglong2 a = *(const ulonglong2*)(whh1 + lane * 32 + i * 4);
        ulonglong2 b = *(const ulonglong2*)(whh1 + (32 + lane) * 32 + i * 4);
        ulonglong2 c = *(const ulonglong2*)(whh1 + (64 + lane) * 32 + i * 4);
        wr[2 * i] = a.x; wr[2 * i + 1] = a.y;
        wz[2 * i] = b.x; wz[2 * i + 1] = b.y;
        wn[2 * i] = c.x; wn[2 * i + 1] = c.y;
    }
    const float bR = bhh1[lane], bZ = bhh1[32 + lane], bN = bhh1[64 + lane];

    const int row = blockIdx.x * 16 + warp;
    float* hw = hs + warp * 32;
    hw[lane] = 0.f;
    float h = 0.f;

    const float* ga = g_gx1 + (size_t)row * TT * 96;
    float f0[3], f1[3];
    f0[0] = ga[lane]; f0[1] = ga[32 + lane]; f0[2] = ga[64 + lane]; ga += 96;
    f1[0] = ga[lane]; f1[1] = ga[32 + lane]; f1[2] = ga[64 + lane]; ga += 96;
    __syncwarp();

#pragma unroll 2
    for (int t = 0; t < TT; t++) {
        float xr, xz, xn;
        if ((t & 1) == 0) { xr = f0[0]; xz = f0[1]; xn = f0[2]; }
        else              { xr = f1[0]; xz = f1[1]; xn = f1[2]; }
        if (t + 2 < TT) {
            if ((t & 1) == 0) { f0[0] = ga[lane]; f0[1] = ga[32 + lane]; f0[2] = ga[64 + lane]; }
            else              { f1[0] = ga[lane]; f1[1] = ga[32 + lane]; f1[2] = ga[64 + lane]; }
            ga += 96;
        }

        u64 gr = pack2(xr + bR, 0.f), gz = pack2(xz + bZ, 0.f), gn = pack2(bN, 0.f);
#pragma unroll
        for (int kk = 0; kk < 8; kk++) {
            ulonglong2 v = *(const ulonglong2*)(hw + kk * 4);
            gr = ffma2(wr[2 * kk], v.x, gr); gr = ffma2(wr[2 * kk + 1], v.y, gr);
            gz = ffma2(wz[2 * kk], v.x, gz); gz = ffma2(wz[2 * kk + 1], v.y, gz);
            gn = ffma2(wn[2 * kk], v.x, gn); gn = ffma2(wn[2 * kk + 1], v.y, gn);
        }
        {
            float r = fast_sigmoid(sum2(gr));
            float z = fast_sigmoid(sum2(gz));
            float n = fast_tanh(xn + r * sum2(gn));
            h = n + z * (h - n);
        }
        __syncwarp();
        hw[lane] = h;
        __syncwarp();
    }

    out[BB + BB * HH + row * HH + lane] = h;   // h_last1
    float p = h * wcls[lane];
#pragma unroll
    for (int off = 16; off; off >>= 1) p += __shfl_xor_sync(0xffffffffu, p, off);
    if (lane == 0) out[row] = fast_sigmoid(p + bcls[0]);
}

extern "C" void kernel_launch(void* const* d_in, const int* in_sizes, int n_in,
                              void* d_out, int out_size) {
    (void)in_sizes; (void)n_in; (void)out_size;
    const float* x    = (const float*)d_in[0];
    const float* wih0 = (const float*)d_in[1];
    const float* whh0 = (const float*)d_in[2];
    const float* bih0 = (const float*)d_in[3];
    const float* bhh0 = (const float*)d_in[4];
    const float* wih1 = (const float*)d_in[5];
    const float* whh1 = (const float*)d_in[6];
    const float* bih1 = (const float*)d_in[7];
    const float* bhh1 = (const float*)d_in[8];
    const float* wcls = (const float*)d_in[9];
    const float* bcls = (const float*)d_in[10];
    float* out = (float*)d_out;

    gx0_kernel<<<BB, 256>>>(x, wih0, bih0);
    rec0_kernel<<<128, 512>>>(whh0, bhh0, out);
    gxl1_kernel<<<BB, 256>>>(wih1, bih1);
    rec1_kernel<<<128, 512>>>(whh1, bhh1, wcls, bcls, out);
}

// round 14
// speedup vs baseline: 1.5165x; 1.5165x over previous
#include <cuda_runtime.h>
#include <cstddef>

#define BB 2048
#define TT 1024
#define DD 64
#define HH 32

typedef unsigned long long u64;

__device__ float g_gx0[(size_t)BB * TT * 96];
__device__ float g_gx1[(size_t)BB * TT * 96];
__device__ float g_h0[(size_t)BB * TT * 32];

__device__ __forceinline__ u64 ffma2(u64 a, u64 b, u64 c) {
    u64 d;
    asm("fma.rn.f32x2 %0, %1, %2, %3;" : "=l"(d) : "l"(a), "l"(b), "l"(c));
    return d;
}
__device__ __forceinline__ u64 pack2(float lo, float hi) {
    u64 r;
    asm("mov.b64 %0, {%1, %2};" : "=l"(r) : "f"(lo), "f"(hi));
    return r;
}
__device__ __forceinline__ float sum2(u64 v) {
    float a, b;
    asm("mov.b64 {%0, %1}, %2;" : "=f"(a), "=f"(b) : "l"(v));
    return a + b;
}
__device__ __forceinline__ float fast_sigmoid(float x) {
    float e;
    asm("ex2.approx.f32 %0, %1;" : "=f"(e) : "f"(-1.4426950408889634f * x));
    float r;
    asm("rcp.approx.f32 %0, %1;" : "=f"(r) : "f"(1.0f + e));
    return r;
}
__device__ __forceinline__ float fast_tanh(float x) {
    return fmaf(2.0f, fast_sigmoid(2.0f * x), -1.0f);
}

// ================= Phase A: gx0 = x @ W_ih0^T + b_ih0 (K=64) — R12-proven =================
__global__ void __launch_bounds__(256, 1)
gx0_kernel(const float* __restrict__ x,
           const float* __restrict__ wih0, const float* __restrict__ bih0)
{
    __shared__ float4 w4[16 * 96];
    __shared__ float4 xs[8 * 128];

    const int tid = threadIdx.x, warp = tid >> 5, lane = tid & 31;
    for (int i = tid; i < 1536; i += 256) {
        int g = i % 96, kk = i / 96;
        w4[kk * 96 + g] = *(const float4*)(wih0 + g * 64 + kk * 4);
    }
    __syncthreads();
    const float b0 = bih0[lane], b1 = bih0[32 + lane], b2 = bih0[64 + lane];

    const int row = blockIdx.x;
    const float4* xg = (const float4*)(x + (size_t)row * TT * DD) + warp * 2048;
    float* gw = g_gx0 + ((size_t)row * TT + warp * 128) * 96;
    float4* xsw = xs + warp * 128;

    float4 xb[4];
#pragma unroll
    for (int i = 0; i < 4; i++) xb[i] = xg[i * 32 + lane];
    xg += 128;

    for (int it = 0; it < 16; it++) {
#pragma unroll
        for (int i = 0; i < 4; i++) xsw[i * 32 + lane] = xb[i];
        __syncwarp();
        if (it + 1 < 16) {
#pragma unroll
            for (int i = 0; i < 4; i++) xb[i] = xg[i * 32 + lane];
            xg += 128;
        }
        u64 a0[8], a1[8], a2[8];
#pragma unroll
        for (int t = 0; t < 8; t++) {
            a0[t] = pack2(b0, 0.f); a1[t] = pack2(b1, 0.f); a2[t] = pack2(b2, 0.f);
        }
#pragma unroll 4
        for (int kk = 0; kk < 16; kk++) {
            ulonglong2 wr = *(const ulonglong2*)(w4 + kk * 96 + lane);
            ulonglong2 wz = *(const ulonglong2*)(w4 + kk * 96 + 32 + lane);
            ulonglong2 wn = *(const ulonglong2*)(w4 + kk * 96 + 64 + lane);
#pragma unroll
            for (int t = 0; t < 8; t++) {
                ulonglong2 xv = *(const ulonglong2*)(xsw + t * 16 + kk);
                a0[t] = ffma2(wr.x, xv.x, a0[t]); a0[t] = ffma2(wr.y, xv.y, a0[t]);
                a1[t] = ffma2(wz.x, xv.x, a1[t]); a1[t] = ffma2(wz.y, xv.y, a1[t]);
                a2[t] = ffma2(wn.x, xv.x, a2[t]); a2[t] = ffma2(wn.y, xv.y, a2[t]);
            }
        }
#pragma unroll
        for (int t = 0; t < 8; t++) {
            float* o = gw + (it * 8 + t) * 96;
            o[lane] = sum2(a0[t]); o[32 + lane] = sum2(a1[t]); o[64 + lane] = sum2(a2[t]);
        }
        __syncwarp();
    }
}

// ================= Phase C: gxl1 = h0_all @ W_ih1^T + b_ih1 (K=32) — R11-proven =================
__global__ void __launch_bounds__(256, 1)
gxl1_kernel(const float* __restrict__ wih1, const float* __restrict__ bih1)
{
    __shared__ float4 w4[8 * 96];
    __shared__ float4 hsh[8 * 64];

    const int tid = threadIdx.x, warp = tid >> 5, lane = tid & 31;
    for (int i = tid; i < 768; i += 256) {
        int g = i % 96, kk = i / 96;
        w4[kk * 96 + g] = *(const float4*)(wih1 + g * 32 + kk * 4);
    }
    __syncthreads();
    const float b0 = bih1[lane], b1 = bih1[32 + lane], b2 = bih1[64 + lane];

    const int row = blockIdx.x;
    const float4* hg = (const float4*)(g_h0 + (size_t)row * TT * 32) + warp * 1024;
    float* gw = g_gx1 + ((size_t)row * TT + warp * 128) * 96;
    float4* hsw = hsh + warp * 64;

    float4 hb[2];
#pragma unroll
    for (int i = 0; i < 2; i++) hb[i] = hg[i * 32 + lane];
    hg += 64;

    for (int it = 0; it < 16; it++) {
#pragma unroll
        for (int i = 0; i < 2; i++) hsw[i * 32 + lane] = hb[i];
        __syncwarp();
        if (it + 1 < 16) {
#pragma unroll
            for (int i = 0; i < 2; i++) hb[i] = hg[i * 32 + lane];
            hg += 64;
        }
        u64 a0[8], a1[8], a2[8];
#pragma unroll
        for (int t = 0; t < 8; t++) {
            a0[t] = pack2(b0, 0.f); a1[t] = pack2(b1, 0.f); a2[t] = pack2(b2, 0.f);
        }
#pragma unroll 4
        for (int kk = 0; kk < 8; kk++) {
            ulonglong2 wr = *(const ulonglong2*)(w4 + kk * 96 + lane);
            ulonglong2 wz = *(const ulonglong2*)(w4 + kk * 96 + 32 + lane);
            ulonglong2 wn = *(const ulonglong2*)(w4 + kk * 96 + 64 + lane);
#pragma unroll
            for (int t = 0; t < 8; t++) {
                ulonglong2 hv = *(const ulonglong2*)(hsw + t * 8 + kk);
                a0[t] = ffma2(wr.x, hv.x, a0[t]); a0[t] = ffma2(wr.y, hv.y, a0[t]);
                a1[t] = ffma2(wz.x, hv.x, a1[t]); a1[t] = ffma2(wz.y, hv.y, a1[t]);
                a2[t] = ffma2(wn.x, hv.x, a2[t]); a2[t] = ffma2(wn.y, hv.y, a2[t]);
            }
        }
#pragma unroll
        for (int t = 0; t < 8; t++) {
            float* o = gw + (it * 8 + t) * 96;
            o[lane] = sum2(a0[t]); o[32 + lane] = sum2(a1[t]); o[64 + lane] = sum2(a2[t]);
        }
        __syncwarp();
    }
}

// recurrence step: 2 rows, register weights, split accumulator chains (2x8).
// b_hh_n (BN) seeds the h-side n accumulator so it lands inside r*(...) per torch GRU.
__device__ __forceinline__ void rec_step(const float* __restrict__ hw,
                                         const u64* __restrict__ wr,
                                         const u64* __restrict__ wz,
                                         const u64* __restrict__ wn,
                                         float xra, float xza, float xna,
                                         float xrb, float xzb, float xnb,
                                         float BN, float& HA, float& HB)
{
    u64 grA = pack2(xra, 0.f), gzA = pack2(xza, 0.f), gnA = pack2(BN, 0.f);
    u64 grB = pack2(xrb, 0.f), gzB = pack2(xzb, 0.f), gnB = pack2(BN, 0.f);
    u64 hrA = pack2(0.f, 0.f), hzA = pack2(0.f, 0.f), hnA = pack2(0.f, 0.f);
    u64 hrB = pack2(0.f, 0.f), hzB = pack2(0.f, 0.f), hnB = pack2(0.f, 0.f);
#pragma unroll
    for (int kk = 0; kk < 4; kk++) {
        ulonglong2 va = *(const ulonglong2*)(hw + kk * 4);
        ulonglong2 vb = *(const ulonglong2*)(hw + 32 + kk * 4);
        grA = ffma2(wr[2*kk], va.x, grA); grA = ffma2(wr[2*kk+1], va.y, grA);
        gzA = ffma2(wz[2*kk], va.x, gzA); gzA = ffma2(wz[2*kk+1], va.y, gzA);
        gnA = ffma2(wn[2*kk], va.x, gnA); gnA = ffma2(wn[2*kk+1], va.y, gnA);
        grB = ffma2(wr[2*kk], vb.x, grB); grB = ffma2(wr[2*kk+1], vb.y, grB);
        gzB = ffma2(wz[2*kk], vb.x, gzB); gzB = ffma2(wz[2*kk+1], vb.y, gzB);
        gnB = ffma2(wn[2*kk], vb.x, gnB); gnB = ffma2(wn[2*kk+1], vb.y, gnB);
    }
#pragma unroll
    for (int kk = 4; kk < 8; kk++) {
        ulonglong2 va = *(const ulonglong2*)(hw + kk * 4);
        ulonglong2 vb = *(const ulonglong2*)(hw + 32 + kk * 4);
        hrA = ffma2(wr[2*kk], va.x, hrA); hrA = ffma2(wr[2*kk+1], va.y, hrA);
        hzA = ffma2(wz[2*kk], va.x, hzA); hzA = ffma2(wz[2*kk+1], va.y, hzA);
        hnA = ffma2(wn[2*kk], va.x, hnA); hnA = ffma2(wn[2*kk+1], va.y, hnA);
        hrB = ffma2(wr[2*kk], vb.x, hrB); hrB = ffma2(wr[2*kk+1], vb.y, hrB);
        hzB = ffma2(wz[2*kk], vb.x, hzB); hzB = ffma2(wz[2*kk+1], vb.y, hzB);
        hnB = ffma2(wn[2*kk], vb.x, hnB); hnB = ffma2(wn[2*kk+1], vb.y, hnB);
    }
    float rA = fast_sigmoid(sum2(grA) + sum2(hrA));
    float zA = fast_sigmoid(sum2(gzA) + sum2(hzA));
    float nA = fast_tanh(xna + rA * (sum2(gnA) + sum2(hnA)));
    HA = nA + zA * (HA - nA);
    float rB = fast_sigmoid(sum2(grB) + sum2(hrB));
    float zB = fast_sigmoid(sum2(gzB) + sum2(hzB));
    float nB = fast_tanh(xnb + rB * (sum2(gnB) + sum2(hnB)));
    HB = nB + zB * (HB - nB);
}

// ================= Phase B: layer-0 recurrence =================
__global__ void __launch_bounds__(256, 1)
rec0_kernel(const float* __restrict__ whh0, const float* __restrict__ bhh0,
            float* __restrict__ out)
{
    __shared__ float hs[512];
    const int tid = threadIdx.x, warp = tid >> 5, lane = tid & 31;
    const int r0 = blockIdx.x * 16 + warp * 2;

    u64 wr[16], wz[16], wn[16];
#pragma unroll
    for (int i = 0; i < 8; i++) {
        ulonglong2 a = *(const ulonglong2*)(whh0 + lane * 32 + i * 4);
        ulonglong2 b = *(const ulonglong2*)(whh0 + (32 + lane) * 32 + i * 4);
        ulonglong2 c = *(const ulonglong2*)(whh0 + (64 + lane) * 32 + i * 4);
        wr[2 * i] = a.x; wr[2 * i + 1] = a.y;
        wz[2 * i] = b.x; wz[2 * i + 1] = b.y;
        wn[2 * i] = c.x; wn[2 * i + 1] = c.y;
    }
    const float bR = bhh0[lane], bZ = bhh0[32 + lane], bN = bhh0[64 + lane];

    float* hw = hs + warp * 64;
    hw[lane] = 0.f; hw[32 + lane] = 0.f;
    float ha = 0.f, hb = 0.f;

    const float* ga = g_gx0 + (size_t)r0 * TT * 96;
    const float* gb = ga + (size_t)TT * 96;
    float* hoA = g_h0 + (size_t)r0 * TT * 32;
    float* hoB = hoA + (size_t)TT * 32;

    float fa[4][3], fb[4][3];
#pragma unroll
    for (int s = 0; s < 4; s++) {
        fa[s][0] = ga[lane]; fa[s][1] = ga[32 + lane]; fa[s][2] = ga[64 + lane]; ga += 96;
        fb[s][0] = gb[lane]; fb[s][1] = gb[32 + lane]; fb[s][2] = gb[64 + lane]; gb += 96;
    }
    __syncwarp();

#pragma unroll 4
    for (int t = 0; t < TT; t++) {
        const int s = t & 3;
        float xra = fa[s][0] + bR, xza = fa[s][1] + bZ, xna = fa[s][2];
        float xrb = fb[s][0] + bR, xzb = fb[s][1] + bZ, xnb = fb[s][2];
        if (t + 4 < TT) {
            fa[s][0] = ga[lane]; fa[s][1] = ga[32 + lane]; fa[s][2] = ga[64 + lane]; ga += 96;
            fb[s][0] = gb[lane]; fb[s][1] = gb[32 + lane]; fb[s][2] = gb[64 + lane]; gb += 96;
        }
        rec_step(hw, wr, wz, wn, xra, xza, xna, xrb, xzb, xnb, bN, ha, hb);
        hoA[t * 32 + lane] = ha;
        hoB[t * 32 + lane] = hb;
        __syncwarp();
        hw[lane] = ha; hw[32 + lane] = hb;
        __syncwarp();
    }
    out[BB + r0 * HH + lane]       = ha;
    out[BB + (r0 + 1) * HH + lane] = hb;
}

// ================= Phase D: layer-1 recurrence + classifier =================
__global__ void __launch_bounds__(256, 1)
rec1_kernel(const float* __restrict__ whh1, const float* __restrict__ bhh1,
            const float* __restrict__ wcls, const float* __restrict__ bcls,
            float* __restrict__ out)
{
    __shared__ float hs[512];
    const int tid = threadIdx.x, warp = tid >> 5, lane = tid & 31;
    const int r0 = blockIdx.x * 16 + warp * 2;

    u64 wr[16], wz[16], wn[16];
#pragma unroll
    for (int i = 0; i < 8; i++) {
        ulonglong2 a = *(const ulonglong2*)(whh1 + lane * 32 + i * 4);
        ulonglong2 b = *(const ulonglong2*)(whh1 + (32 + lane) * 32 + i * 4);
        ulonglong2 c = *(const ulonglong2*)(whh1 + (64 + lane) * 32 + i * 4);
        wr[2 * i] = a.x; wr[2 * i + 1] = a.y;
        wz[2 * i] = b.x; wz[2 * i + 1] = b.y;
        wn[2 * i] = c.x; wn[2 * i + 1] = c.y;
    }
    const float bR = bhh1[lane], bZ = bhh1[32 + lane], bN = bhh1[64 + lane];

    float* hw = hs + warp * 64;
    hw[lane] = 0.f; hw[32 + lane] = 0.f;
    float ha = 0.f, hb = 0.f;

    const float* ga = g_gx1 + (size_t)r0 * TT * 96;
    const float* gb = ga + (size_t)TT * 96;

    float fa[4][3], fb[4][3];
#pragma unroll
    for (int s = 0; s < 4; s++) {
        fa[s][0] = ga[lane]; fa[s][1] = ga[32 + lane]; fa[s][2] = ga[64 + lane]; ga += 96;
        fb[s][0] = gb[lane]; fb[s][1] = gb[32 + lane]; fb[s][2] = gb[64 + lane]; gb += 96;
    }
    __syncwarp();

#pragma unroll 4
    for (int t = 0; t < TT; t++) {
        const int s = t & 3;
        float xra = fa[s][0] + bR, xza = fa[s][1] + bZ, xna = fa[s][2];
        float xrb = fb[s][0] + bR, xzb = fb[s][1] + bZ, xnb = fb[s][2];
        if (t + 4 < TT) {
            fa[s][0] = ga[lane]; fa[s][1] = ga[32 + lane]; fa[s][2] = ga[64 + lane]; ga += 96;
            fb[s][0] = gb[lane]; fb[s][1] = gb[32 + lane]; fb[s][2] = gb[64 + lane]; gb += 96;
        }
        rec_step(hw, wr, wz, wn, xra, xza, xna, xrb, xzb, xnb, bN, ha, hb);
        __syncwarp();
        hw[lane] = ha; hw[32 + lane] = hb;
        __syncwarp();
    }

    out[BB + BB * HH + r0 * HH + lane]       = ha;
    out[BB + BB * HH + (r0 + 1) * HH + lane] = hb;
    const float wc = wcls[lane];
    float pA = ha * wc, pB = hb * wc;
#pragma unroll
    for (int off = 16; off; off >>= 1) {
        pA += __shfl_xor_sync(0xffffffffu, pA, off);
        pB += __shfl_xor_sync(0xffffffffu, pB, off);
    }
    if (lane == 0) {
        float bc = bcls[0];
        out[r0]     = fast_sigmoid(pA + bc);
        out[r0 + 1] = fast_sigmoid(pB + bc);
    }
}

extern "C" void kernel_launch(void* const* d_in, const int* in_sizes, int n_in,
                              void* d_out, int out_size) {
    (void)in_sizes; (void)n_in; (void)out_size;
    const float* x    = (const float*)d_in[0];
    const float* wih0 = (const float*)d_in[1];
    const float* whh0 = (const float*)d_in[2];
    const float* bih0 = (const float*)d_in[3];
    const float* bhh0 = (const float*)d_in[4];
    const float* wih1 = (const float*)d_in[5];
    const float* whh1 = (const float*)d_in[6];
    const float* bih1 = (const float*)d_in[7];
    const float* bhh1 = (const float*)d_in[8];
    const float* wcls = (const float*)d_in[9];
    const float* bcls = (const float*)d_in[10];
    float* out = (float*)d_out;

    gx0_kernel<<<BB, 256>>>(x, wih0, bih0);
    rec0_kernel<<<128, 256>>>(whh0, bhh0, out);
    gxl1_kernel<<<BB, 256>>>(wih1, bih1);
    rec1_kernel<<<128, 256>>>(whh1, bhh1, wcls, bcls, out);
}